// round 7
// baseline (speedup 1.0000x reference)
#include <cuda_runtime.h>
#include <cuda_bf16.h>
#include <math.h>

// ---------------- problem constants ----------------
#define B_       2
#define NQ_      1600
#define D_       256
#define H_       8
#define HD_      32
#define L_       4
#define P_       4
#define DFFN_    1024
#define STOT_    5440
#define MROWS_   (B_*NQ_)          // 3200
#define MSRC_    (B_*STOT_)        // 10880
#define XSZ_     (MROWS_*D_)       // 819200
#define NLAYERS_ 6

// ---------------- device scratch (static, no allocation) ----------------
__device__ float g_x  [XSZ_];
__device__ float g_q  [XSZ_];
__device__ float g_qh [XSZ_];
__device__ float g_kh [XSZ_];
__device__ float g_vh [XSZ_];
__device__ float g_t  [XSZ_];
__device__ float g_t2 [XSZ_];
__device__ float g_off[XSZ_];
__device__ float g_aw [MROWS_*128];
__device__ float g_val[MSRC_*D_];
__device__ float g_ffn[MROWS_*DFFN_];

// ---------------- elementwise ----------------
__global__ void copy_kernel(float* __restrict__ dst, const float* __restrict__ s, int n) {
    int i = blockIdx.x * 256 + threadIdx.x;
    if (i < n) dst[i] = s[i];
}
__global__ void add_kernel(float* __restrict__ dst, const float* __restrict__ a,
                           const float* __restrict__ b, int n) {
    int i = blockIdx.x * 256 + threadIdx.x;
    if (i < n) dst[i] = a[i] + b[i];
}

// ---------------- GEMM: C[M,N] = A[M,K] * W[N,K]^T + bias ----------------
// Requires M%64==0, N%64==0, K%16==0 (true for every call here).
template<bool RELU>
__global__ void gemm_bias_kernel(const float* __restrict__ A, const float* __restrict__ W,
                                 const float* __restrict__ bias, float* __restrict__ C,
                                 int M, int N, int K) {
    __shared__ float As[16][65];
    __shared__ float Ws[16][65];
    const int tid = threadIdx.x;
    const int tx = tid & 15, ty = tid >> 4;
    const int m0 = blockIdx.y * 64, n0 = blockIdx.x * 64;
    float acc[4][4] = {};
    const int r  = tid >> 2;          // 0..63
    const int c4 = (tid & 3) * 4;     // 0,4,8,12
    for (int k0 = 0; k0 < K; k0 += 16) {
        float4 a = *(const float4*)(A + (size_t)(m0 + r) * K + k0 + c4);
        As[c4+0][r] = a.x; As[c4+1][r] = a.y; As[c4+2][r] = a.z; As[c4+3][r] = a.w;
        float4 w = *(const float4*)(W + (size_t)(n0 + r) * K + k0 + c4);
        Ws[c4+0][r] = w.x; Ws[c4+1][r] = w.y; Ws[c4+2][r] = w.z; Ws[c4+3][r] = w.w;
        __syncthreads();
        #pragma unroll
        for (int k = 0; k < 16; k++) {
            float av[4], bv[4];
            #pragma unroll
            for (int i = 0; i < 4; i++) av[i] = As[k][ty*4 + i];
            #pragma unroll
            for (int j = 0; j < 4; j++) bv[j] = Ws[k][tx*4 + j];
            #pragma unroll
            for (int i = 0; i < 4; i++)
                #pragma unroll
                for (int j = 0; j < 4; j++)
                    acc[i][j] += av[i] * bv[j];
        }
        __syncthreads();
    }
    #pragma unroll
    for (int i = 0; i < 4; i++) {
        const int m = m0 + ty*4 + i;
        #pragma unroll
        for (int j = 0; j < 4; j++) {
            const int n = n0 + tx*4 + j;
            float v = acc[i][j] + bias[n];
            if (RELU) v = fmaxf(v, 0.f);
            C[(size_t)m * N + n] = v;
        }
    }
}

// ---------------- fused self-attention (flash-style, fp32) ----------------
// grid = (NQ/32, H, B), block = 256. qh/kh/vh layout: (B, N, H*HD) row-major.
__global__ void attn_kernel(const float* __restrict__ qh, const float* __restrict__ kh,
                            const float* __restrict__ vh, float* __restrict__ out) {
    __shared__ float4 Ks[64 * 8];
    __shared__ float4 Vs[64 * 8];
    const int qt = blockIdx.x, h = blockIdx.y, b = blockIdx.z;
    const int tid = threadIdx.x;
    const int ql = tid >> 3, sub = tid & 7;
    const size_t bbase = (size_t)b * NQ_ * D_ + h * HD_;
    const int q = qt * 32 + ql;
    const float4 qreg = *(const float4*)(qh + bbase + (size_t)q * D_ + sub * 4);
    const float scale = 0.17677669529663687f; // 1/sqrt(32)
    float m = -INFINITY, lsum = 0.f;
    float4 acc = make_float4(0.f, 0.f, 0.f, 0.f);
    for (int kt = 0; kt < NQ_ / 64; kt++) {
        __syncthreads();
        #pragma unroll
        for (int i = 0; i < 2; i++) {
            int e = tid + i * 256;
            int kr = e >> 3, c = e & 7;
            size_t ga = bbase + (size_t)(kt * 64 + kr) * D_ + c * 4;
            Ks[e] = *(const float4*)(kh + ga);
            Vs[e] = *(const float4*)(vh + ga);
        }
        __syncthreads();
        #pragma unroll 4
        for (int k = 0; k < 64; k++) {
            float4 kk = Ks[k * 8 + sub];
            float p = qreg.x*kk.x + qreg.y*kk.y + qreg.z*kk.z + qreg.w*kk.w;
            p += __shfl_xor_sync(0xffffffffu, p, 1);
            p += __shfl_xor_sync(0xffffffffu, p, 2);
            p += __shfl_xor_sync(0xffffffffu, p, 4);
            float sc = p * scale;
            float mn = fmaxf(m, sc);
            float corr = __expf(m - mn);
            float e2 = __expf(sc - mn);
            lsum = lsum * corr + e2;
            float4 vv = Vs[k * 8 + sub];
            acc.x = acc.x * corr + e2 * vv.x;
            acc.y = acc.y * corr + e2 * vv.y;
            acc.z = acc.z * corr + e2 * vv.z;
            acc.w = acc.w * corr + e2 * vv.w;
            m = mn;
        }
    }
    const float inv = 1.f / lsum;
    float4 o = make_float4(acc.x*inv, acc.y*inv, acc.z*inv, acc.w*inv);
    *(float4*)(out + bbase + (size_t)q * D_ + sub * 4) = o;
}

// ---------------- softmax over 16 (deform attn weights) ----------------
__global__ void softmax16_kernel(float* __restrict__ aw, int rows) {
    int r = blockIdx.x * 256 + threadIdx.x;
    if (r >= rows) return;
    float* p = aw + (size_t)r * 16;
    float v[16];
    float mx = -INFINITY;
    #pragma unroll
    for (int i = 0; i < 16; i++) { v[i] = p[i]; mx = fmaxf(mx, v[i]); }
    float s = 0.f;
    #pragma unroll
    for (int i = 0; i < 16; i++) { v[i] = __expf(v[i] - mx); s += v[i]; }
    const float inv = 1.f / s;
    #pragma unroll
    for (int i = 0; i < 16; i++) p[i] = v[i] * inv;
}

// ---------------- MS deformable sampling ----------------
// grid = B*NQ, block = 256 (thread = h*32 + hd).
__global__ void msda_kernel(const float* __restrict__ val, const float* __restrict__ off,
                            const float* __restrict__ aw, const float* __restrict__ refp,
                            float* __restrict__ out) {
    const int bq = blockIdx.x;
    const int b = bq / NQ_;
    const int tid = threadIdx.x;
    const int h = tid >> 5;
    const int hd = tid & 31;
    const float* offr = off + (size_t)bq * 256;
    const float* awr  = aw  + (size_t)bq * 128;
    const float* rr   = refp + (size_t)bq * 8;
    const float* vb   = val + (size_t)b * STOT_ * D_;
    float acc = 0.f;
    const int LVL_W[4]  = {64, 32, 16, 8};
    const int LVL_S0[4] = {0, 4096, 5120, 5376};
    #pragma unroll
    for (int l = 0; l < 4; l++) {
        const int Wl = LVL_W[l];
        const float Wf = (float)Wl;
        const int s0 = LVL_S0[l];
        const float rx = rr[l*2 + 0];
        const float ry = rr[l*2 + 1];
        #pragma unroll
        for (int p = 0; p < 4; p++) {
            const int oi = (((h*4 + l)*4) + p) * 2;
            const float locx = rx + offr[oi + 0] / Wf;
            const float locy = ry + offr[oi + 1] / Wf;   // H == W per level
            const float xx = locx * Wf - 0.5f;
            const float yy = locy * Wf - 0.5f;
            const float x0 = floorf(xx), y0 = floorf(yy);
            const float wx1 = xx - x0, wy1 = yy - y0;
            float sampv = 0.f;
            #pragma unroll
            for (int dy = 0; dy < 2; dy++) {
                const float yi = y0 + (float)dy;
                const float wy = dy ? wy1 : (1.f - wy1);
                #pragma unroll
                for (int dx = 0; dx < 2; dx++) {
                    const float xi = x0 + (float)dx;
                    const float wx = dx ? wx1 : (1.f - wx1);
                    const bool valid = (xi >= 0.f) && (xi <= Wf - 1.f) &&
                                       (yi >= 0.f) && (yi <= Wf - 1.f);
                    const float w = wx * wy * (valid ? 1.f : 0.f);
                    if (w != 0.f) {
                        const int xic = (int)fminf(fmaxf(xi, 0.f), Wf - 1.f);
                        const int yic = (int)fminf(fmaxf(yi, 0.f), Wf - 1.f);
                        const float g = vb[(size_t)(s0 + yic * Wl + xic) * D_ + h * HD_ + hd];
                        sampv += g * w;
                    }
                }
            }
            acc += sampv * awr[h*16 + l*4 + p];
        }
    }
    out[(size_t)bq * D_ + tid] = acc;
}

// ---------------- residual + layernorm: dst = LN(a + b) ----------------
// grid = rows, block = 256 (= D_).
__global__ void ln_kernel(float* __restrict__ dst, const float* __restrict__ a,
                          const float* __restrict__ bsrc, const float* __restrict__ g,
                          const float* __restrict__ beta) {
    const int row = blockIdx.x;
    const int c = threadIdx.x;
    const float v = a[(size_t)row * D_ + c] + bsrc[(size_t)row * D_ + c];
    __shared__ float red[8];
    __shared__ float sh_mu, sh_var;
    float s = v;
    #pragma unroll
    for (int o = 16; o; o >>= 1) s += __shfl_xor_sync(0xffffffffu, s, o);
    if ((c & 31) == 0) red[c >> 5] = s;
    __syncthreads();
    if (c == 0) {
        float t = 0.f;
        #pragma unroll
        for (int i = 0; i < 8; i++) t += red[i];
        sh_mu = t * (1.f / 256.f);
    }
    __syncthreads();
    const float mu = sh_mu;
    const float d = v - mu;
    s = d * d;
    #pragma unroll
    for (int o = 16; o; o >>= 1) s += __shfl_xor_sync(0xffffffffu, s, o);
    if ((c & 31) == 0) red[c >> 5] = s;
    __syncthreads();
    if (c == 0) {
        float t = 0.f;
        #pragma unroll
        for (int i = 0; i < 8; i++) t += red[i];
        sh_var = t * (1.f / 256.f);
    }
    __syncthreads();
    const float y = d * rsqrtf(sh_var + 1e-5f) * g[c] + beta[c];
    dst[(size_t)row * D_ + c] = y;
}

// ---------------- host orchestration ----------------
extern "C" void kernel_launch(void* const* d_in, const int* in_sizes, int n_in,
                              void* d_out, int out_size) {
    (void)in_sizes; (void)n_in; (void)out_size;
    const float* tgt      = (const float*)d_in[0];
    const float* qpos     = (const float*)d_in[1];
    const float* refp     = (const float*)d_in[2];
    const float* src      = (const float*)d_in[3];
    const float* sa_w_q   = (const float*)d_in[4];
    const float* sa_b_q   = (const float*)d_in[5];
    const float* sa_w_k   = (const float*)d_in[6];
    const float* sa_b_k   = (const float*)d_in[7];
    const float* sa_w_v   = (const float*)d_in[8];
    const float* sa_b_v   = (const float*)d_in[9];
    const float* sa_w_o   = (const float*)d_in[10];
    const float* sa_b_o   = (const float*)d_in[11];
    const float* ln2_g    = (const float*)d_in[12];
    const float* ln2_b    = (const float*)d_in[13];
    const float* ca_w_off = (const float*)d_in[14];
    const float* ca_b_off = (const float*)d_in[15];
    const float* ca_w_attn= (const float*)d_in[16];
    const float* ca_b_attn= (const float*)d_in[17];
    const float* ca_w_val = (const float*)d_in[18];
    const float* ca_b_val = (const float*)d_in[19];
    const float* ca_w_out = (const float*)d_in[20];
    const float* ca_b_out = (const float*)d_in[21];
    const float* ln1_g    = (const float*)d_in[22];
    const float* ln1_b    = (const float*)d_in[23];
    const float* ffn_w1   = (const float*)d_in[24];
    const float* ffn_b1   = (const float*)d_in[25];
    const float* ffn_w2   = (const float*)d_in[26];
    const float* ffn_b2   = (const float*)d_in[27];
    const float* ln3_g    = (const float*)d_in[28];
    const float* ln3_b    = (const float*)d_in[29];
    // d_in[30], d_in[31]: spatial shapes / level starts (compile-time constants here)

    float *x, *q, *qh, *kh, *vh, *t, *t2, *off, *aw, *val, *ffn;
    cudaGetSymbolAddress((void**)&x,   g_x);
    cudaGetSymbolAddress((void**)&q,   g_q);
    cudaGetSymbolAddress((void**)&qh,  g_qh);
    cudaGetSymbolAddress((void**)&kh,  g_kh);
    cudaGetSymbolAddress((void**)&vh,  g_vh);
    cudaGetSymbolAddress((void**)&t,   g_t);
    cudaGetSymbolAddress((void**)&t2,  g_t2);
    cudaGetSymbolAddress((void**)&off, g_off);
    cudaGetSymbolAddress((void**)&aw,  g_aw);
    cudaGetSymbolAddress((void**)&val, g_val);
    cudaGetSymbolAddress((void**)&ffn, g_ffn);

    const int EW_BLOCKS = (XSZ_ + 255) / 256;
    copy_kernel<<<EW_BLOCKS, 256>>>(x, tgt, XSZ_);

    const dim3 G256(D_/64, MROWS_/64);      // (4, 50)   N=256
    const dim3 G128(128/64, MROWS_/64);     // (2, 50)   N=128
    const dim3 G1024(DFFN_/64, MROWS_/64);  // (16, 50)  N=1024
    const dim3 GVAL(D_/64, MSRC_/64);       // (4, 170)
    const dim3 GATTN(NQ_/32, H_, B_);       // (50, 8, 2)

    for (int i = 0; i < NLAYERS_; i++) {
        const float* wq = sa_w_q + (size_t)i*D_*D_;   const float* bq = sa_b_q + i*D_;
        const float* wk = sa_w_k + (size_t)i*D_*D_;   const float* bk = sa_b_k + i*D_;
        const float* wv = sa_w_v + (size_t)i*D_*D_;   const float* bv = sa_b_v + i*D_;
        const float* wo = sa_w_o + (size_t)i*D_*D_;   const float* bo = sa_b_o + i*D_;
        const float* woff = ca_w_off + (size_t)i*D_*D_;     const float* boff = ca_b_off + i*D_;
        const float* watt = ca_w_attn + (size_t)i*128*D_;   const float* batt = ca_b_attn + i*128;
        const float* wval = ca_w_val + (size_t)i*D_*D_;     const float* bval = ca_b_val + i*D_;
        const float* wco  = ca_w_out + (size_t)i*D_*D_;     const float* bco  = ca_b_out + i*D_;
        const float* w1 = ffn_w1 + (size_t)i*DFFN_*D_;      const float* b1 = ffn_b1 + i*DFFN_;
        const float* w2 = ffn_w2 + (size_t)i*D_*DFFN_;      const float* b2 = ffn_b2 + i*D_;

        // ---- self attention ----
        add_kernel<<<EW_BLOCKS, 256>>>(q, x, qpos, XSZ_);
        gemm_bias_kernel<false><<<G256, 256>>>(q, wq, bq, qh, MROWS_, D_, D_);
        gemm_bias_kernel<false><<<G256, 256>>>(q, wk, bk, kh, MROWS_, D_, D_);
        gemm_bias_kernel<false><<<G256, 256>>>(x, wv, bv, vh, MROWS_, D_, D_);
        attn_kernel<<<GATTN, 256>>>(qh, kh, vh, t);
        gemm_bias_kernel<false><<<G256, 256>>>(t, wo, bo, t2, MROWS_, D_, D_);
        ln_kernel<<<MROWS_, 256>>>(x, x, t2, ln2_g + i*D_, ln2_b + i*D_);

        // ---- deformable cross attention ----
        add_kernel<<<EW_BLOCKS, 256>>>(q, x, qpos, XSZ_);
        gemm_bias_kernel<false><<<GVAL, 256>>>(src, wval, bval, val, MSRC_, D_, D_);
        gemm_bias_kernel<false><<<G256, 256>>>(q, woff, boff, off, MROWS_, D_, D_);
        gemm_bias_kernel<false><<<G128, 256>>>(q, watt, batt, aw, MROWS_, 128, D_);
        softmax16_kernel<<<(MROWS_*H_ + 255)/256, 256>>>(aw, MROWS_*H_);
        msda_kernel<<<MROWS_, 256>>>(val, off, aw, refp, t);
        gemm_bias_kernel<false><<<G256, 256>>>(t, wco, bco, t2, MROWS_, D_, D_);
        ln_kernel<<<MROWS_, 256>>>(x, x, t2, ln1_g + i*D_, ln1_b + i*D_);

        // ---- FFN ----
        gemm_bias_kernel<true ><<<G1024, 256>>>(x, w1, b1, ffn, MROWS_, DFFN_, D_);
        gemm_bias_kernel<false><<<G256,  256>>>(ffn, w2, b2, t2, MROWS_, D_, DFFN_);
        float* dst = (i == NLAYERS_ - 1) ? (float*)d_out : x;
        ln_kernel<<<MROWS_, 256>>>(dst, x, t2, ln3_g + i*D_, ln3_b + i*D_);
    }
}

// round 8
// speedup vs baseline: 1.2723x; 1.2723x over previous
#include <cuda_runtime.h>
#include <cuda_bf16.h>
#include <math.h>

// ---------------- problem constants ----------------
#define B_       2
#define NQ_      1600
#define D_       256
#define H_       8
#define HD_      32
#define DFFN_    1024
#define STOT_    5440
#define MROWS_   (B_*NQ_)          // 3200
#define MSRC_    (B_*STOT_)        // 10880
#define XSZ_     (MROWS_*D_)       // 819200
#define NLAYERS_ 6

// ---------------- device scratch (static, no allocation) ----------------
__device__ float g_x  [XSZ_];
__device__ float g_q  [XSZ_];
__device__ float g_qh [XSZ_];
__device__ float g_kh [XSZ_];
__device__ float g_vh [XSZ_];
__device__ float g_t  [XSZ_];
__device__ float g_t2 [XSZ_];
__device__ float g_off[XSZ_];
__device__ float g_aw [MROWS_*128];
__device__ float g_val[MSRC_*D_];
__device__ float g_ffn[MROWS_*DFFN_];

// ---------------- f32x2 packed-math helpers (sm_100+) ----------------
__device__ __forceinline__ unsigned long long pack2(float x) {
    unsigned long long r;
    unsigned int u = __float_as_uint(x);
    asm("mov.b64 %0, {%1, %1};" : "=l"(r) : "r"(u));
    return r;
}
__device__ __forceinline__ void fma2(unsigned long long& d, unsigned long long a, unsigned long long b) {
    asm("fma.rn.f32x2 %0, %1, %2, %0;" : "+l"(d) : "l"(a), "l"(b));
}
__device__ __forceinline__ void mul2(unsigned long long& d, unsigned long long a) {
    asm("mul.rn.f32x2 %0, %0, %1;" : "+l"(d) : "l"(a));
}
__device__ __forceinline__ void add2(unsigned long long& d, unsigned long long a) {
    asm("add.rn.f32x2 %0, %0, %1;" : "+l"(d) : "l"(a));
}
__device__ __forceinline__ float2 unpack2(unsigned long long v) {
    unsigned int lo, hi;
    asm("mov.b64 {%0, %1}, %2;" : "=r"(lo), "=r"(hi) : "l"(v));
    return make_float2(__uint_as_float(lo), __uint_as_float(hi));
}

// ---------------- elementwise ----------------
__global__ void copy_kernel(float* __restrict__ dst, const float* __restrict__ s, int n) {
    int i = blockIdx.x * 256 + threadIdx.x;
    if (i < n) dst[i] = s[i];
}
__global__ void add_kernel(float* __restrict__ dst, const float* __restrict__ a,
                           const float* __restrict__ b, int n) {
    int i = blockIdx.x * 256 + threadIdx.x;
    if (i < n) dst[i] = a[i] + b[i];
}

// ---------------- GEMM: C[M,N] = A[M,K] * W[N,K]^T + bias ----------------
// Tile 128x64, BK=16, 256 threads, 8x4 micro-tile via FFMA2 (m-paired accs).
// Requires M%128==0, N%64==0, K%16==0 (holds for every call site).
template<bool RELU>
__launch_bounds__(256)
__global__ void gemm2_kernel(const float* __restrict__ A, const float* __restrict__ W,
                             const float* __restrict__ bias, float* __restrict__ C,
                             int M, int N, int K) {
    __shared__ float As[2][16][128];
    __shared__ float Ws[2][16][64];
    const int tid = threadIdx.x;
    const int tx = tid & 15, ty = tid >> 4;      // tx: n group, ty: m group
    const int m0 = blockIdx.y * 128, n0 = blockIdx.x * 64;
    const int r  = tid >> 2;                     // row within tile (0..63)
    const int f  = tid & 3;                      // k-chunk (float4) index
    const int sw = f << 3;                       // store swizzle
    const float* Ap0 = A + (size_t)(m0 + r) * K + f * 4;
    const float* Ap1 = Ap0 + (size_t)64 * K;
    const float* Wp  = W + (size_t)(n0 + r) * K + f * 4;

    unsigned long long acc[4][4];
    #pragma unroll
    for (int i = 0; i < 4; i++)
        #pragma unroll
        for (int j = 0; j < 4; j++) acc[i][j] = 0ull;

    // stage tile 0
    float4 a0 = *(const float4*)Ap0;
    float4 a1 = *(const float4*)Ap1;
    float4 w0 = *(const float4*)Wp;
    {
        const int k4 = f * 4;
        As[0][k4+0][r ^ sw] = a0.x; As[0][k4+1][r ^ sw] = a0.y;
        As[0][k4+2][r ^ sw] = a0.z; As[0][k4+3][r ^ sw] = a0.w;
        As[0][k4+0][(r+64) ^ sw] = a1.x; As[0][k4+1][(r+64) ^ sw] = a1.y;
        As[0][k4+2][(r+64) ^ sw] = a1.z; As[0][k4+3][(r+64) ^ sw] = a1.w;
        Ws[0][k4+0][r ^ sw] = w0.x; Ws[0][k4+1][r ^ sw] = w0.y;
        Ws[0][k4+2][r ^ sw] = w0.z; Ws[0][k4+3][r ^ sw] = w0.w;
    }
    __syncthreads();

    const int nit = K >> 4;
    const int ty8 = ty * 8, tx4 = tx * 4;
    for (int it = 0; it < nit; ++it) {
        const int buf = it & 1;
        if (it + 1 < nit) {
            const int ko = (it + 1) << 4;
            a0 = *(const float4*)(Ap0 + ko);
            a1 = *(const float4*)(Ap1 + ko);
            w0 = *(const float4*)(Wp  + ko);
        }
        #pragma unroll
        for (int k = 0; k < 16; k++) {
            const int sk = ((k >> 2) & 3) << 3;
            const float* ap = &As[buf][k][ty8 ^ sk];
            ulonglong2 aA = *(const ulonglong2*)ap;        // m +0..3
            ulonglong2 aB = *(const ulonglong2*)(ap + 4);  // m +4..7
            float4 bv = *(const float4*)&Ws[buf][k][tx4 ^ sk];
            unsigned long long b0 = pack2(bv.x), b1 = pack2(bv.y),
                               b2 = pack2(bv.z), b3 = pack2(bv.w);
            fma2(acc[0][0], aA.x, b0); fma2(acc[0][1], aA.x, b1);
            fma2(acc[0][2], aA.x, b2); fma2(acc[0][3], aA.x, b3);
            fma2(acc[1][0], aA.y, b0); fma2(acc[1][1], aA.y, b1);
            fma2(acc[1][2], aA.y, b2); fma2(acc[1][3], aA.y, b3);
            fma2(acc[2][0], aB.x, b0); fma2(acc[2][1], aB.x, b1);
            fma2(acc[2][2], aB.x, b2); fma2(acc[2][3], aB.x, b3);
            fma2(acc[3][0], aB.y, b0); fma2(acc[3][1], aB.y, b1);
            fma2(acc[3][2], aB.y, b2); fma2(acc[3][3], aB.y, b3);
        }
        if (it + 1 < nit) {
            const int nb = buf ^ 1;
            const int k4 = f * 4;
            As[nb][k4+0][r ^ sw] = a0.x; As[nb][k4+1][r ^ sw] = a0.y;
            As[nb][k4+2][r ^ sw] = a0.z; As[nb][k4+3][r ^ sw] = a0.w;
            As[nb][k4+0][(r+64) ^ sw] = a1.x; As[nb][k4+1][(r+64) ^ sw] = a1.y;
            As[nb][k4+2][(r+64) ^ sw] = a1.z; As[nb][k4+3][(r+64) ^ sw] = a1.w;
            Ws[nb][k4+0][r ^ sw] = w0.x; Ws[nb][k4+1][r ^ sw] = w0.y;
            Ws[nb][k4+2][r ^ sw] = w0.z; Ws[nb][k4+3][r ^ sw] = w0.w;
        }
        __syncthreads();
    }

    // epilogue
    const float4 bb4 = *(const float4*)&bias[n0 + tx4];
    const float bb[4] = {bb4.x, bb4.y, bb4.z, bb4.w};
    #pragma unroll
    for (int j = 0; j < 4; j++) {
        const int n = n0 + tx4 + j;
        #pragma unroll
        for (int i = 0; i < 4; i++) {
            float2 v = unpack2(acc[i][j]);
            float o0 = v.x + bb[j], o1 = v.y + bb[j];
            if (RELU) { o0 = fmaxf(o0, 0.f); o1 = fmaxf(o1, 0.f); }
            const int m = m0 + ty8 + i * 2;
            C[(size_t)m * N + n]       = o0;
            C[(size_t)(m + 1) * N + n] = o1;
        }
    }
}

// ---------------- fused self-attention (flash, FFMA2, fp32) ----------------
// grid = (NQ/32, H, B), block = 256. Thread (ql = tid>>3, sub = tid&7).
// Each thread computes 8 full scores per 64-key tile (no per-score shfl);
// butterfly reduction across the 8 subs only at the end.
__launch_bounds__(256)
__global__ void attn2_kernel(const float* __restrict__ qh, const float* __restrict__ kh,
                             const float* __restrict__ vh, float* __restrict__ out) {
    __shared__ float Ks[64][36];
    __shared__ float Vs[64][36];
    const int qt = blockIdx.x, h = blockIdx.y, b = blockIdx.z;
    const int tid = threadIdx.x;
    const int ql = tid >> 3, sub = tid & 7;
    const size_t bbase = (size_t)b * NQ_ * D_ + h * HD_;
    const int q = qt * 32 + ql;
    const float* qrow = qh + bbase + (size_t)q * D_;

    unsigned long long q2[16];
    #pragma unroll
    for (int p = 0; p < 8; p++) {
        ulonglong2 t = *(const ulonglong2*)(qrow + p * 4);
        q2[2*p] = t.x; q2[2*p+1] = t.y;
    }
    unsigned long long o2[16];
    #pragma unroll
    for (int p = 0; p < 16; p++) o2[p] = 0ull;

    const float scale = 0.17677669529663687f; // 1/sqrt(32)
    float m = -1e30f, lsum = 0.f;

    for (int kt = 0; kt < NQ_ / 64; kt++) {
        __syncthreads();
        #pragma unroll
        for (int i = 0; i < 2; i++) {
            int e = tid + i * 256;          // float4 unit, 0..511
            int kr = e >> 3, dc = (e & 7) * 4;
            size_t ga = bbase + (size_t)(kt * 64 + kr) * D_ + dc;
            *(float4*)&Ks[kr][dc] = *(const float4*)(kh + ga);
            *(float4*)&Vs[kr][dc] = *(const float4*)(vh + ga);
        }
        __syncthreads();

        float s[8];
        #pragma unroll
        for (int j = 0; j < 8; j++) {
            const float* kp = &Ks[j * 8 + sub][0];
            unsigned long long c0 = 0ull, c1 = 0ull;
            #pragma unroll
            for (int p = 0; p < 8; p++) {
                ulonglong2 kk = *(const ulonglong2*)(kp + p * 4);
                fma2(c0, q2[2*p],   kk.x);
                fma2(c1, q2[2*p+1], kk.y);
            }
            float2 r0 = unpack2(c0), r1 = unpack2(c1);
            s[j] = ((r0.x + r0.y) + (r1.x + r1.y)) * scale;
        }
        float tmax = s[0];
        #pragma unroll
        for (int j = 1; j < 8; j++) tmax = fmaxf(tmax, s[j]);
        tmax = fmaxf(tmax, __shfl_xor_sync(0xffffffffu, tmax, 1));
        tmax = fmaxf(tmax, __shfl_xor_sync(0xffffffffu, tmax, 2));
        tmax = fmaxf(tmax, __shfl_xor_sync(0xffffffffu, tmax, 4));

        const float mnew = fmaxf(m, tmax);
        const float corr = __expf(m - mnew);
        m = mnew;
        lsum *= corr;
        const unsigned long long c2 = pack2(corr);
        #pragma unroll
        for (int p = 0; p < 16; p++) mul2(o2[p], c2);

        #pragma unroll
        for (int j = 0; j < 8; j++) {
            const float e = __expf(s[j] - m);
            lsum += e;
            const unsigned long long e2 = pack2(e);
            const float* vp = &Vs[j * 8 + sub][0];
            #pragma unroll
            for (int p = 0; p < 8; p++) {
                ulonglong2 vv = *(const ulonglong2*)(vp + p * 4);
                fma2(o2[2*p],   e2, vv.x);
                fma2(o2[2*p+1], e2, vv.y);
            }
        }
    }

    // reduce across the 8 subs (m is already shared)
    #pragma unroll
    for (int st = 1; st < 8; st <<= 1) {
        lsum += __shfl_xor_sync(0xffffffffu, lsum, st);
        #pragma unroll
        for (int p = 0; p < 16; p++) {
            unsigned long long ot = __shfl_xor_sync(0xffffffffu, o2[p], st);
            add2(o2[p], ot);
        }
    }
    const unsigned long long inv2 = pack2(1.f / lsum);
    unsigned long long oa = o2[sub * 2], ob = o2[sub * 2 + 1];
    mul2(oa, inv2); mul2(ob, inv2);
    float2 r0 = unpack2(oa), r1 = unpack2(ob);
    *(float4*)(out + bbase + (size_t)q * D_ + sub * 4) = make_float4(r0.x, r0.y, r1.x, r1.y);
}

// ---------------- softmax over 16 (deform attn weights) ----------------
__global__ void softmax16_kernel(float* __restrict__ aw, int rows) {
    int r = blockIdx.x * 256 + threadIdx.x;
    if (r >= rows) return;
    float* p = aw + (size_t)r * 16;
    float v[16];
    float mx = -INFINITY;
    #pragma unroll
    for (int i = 0; i < 16; i++) { v[i] = p[i]; mx = fmaxf(mx, v[i]); }
    float s = 0.f;
    #pragma unroll
    for (int i = 0; i < 16; i++) { v[i] = __expf(v[i] - mx); s += v[i]; }
    const float inv = 1.f / s;
    #pragma unroll
    for (int i = 0; i < 16; i++) p[i] = v[i] * inv;
}

// ---------------- MS deformable sampling ----------------
// grid = B*NQ, block = 256 (thread = h*32 + hd).
__global__ void msda_kernel(const float* __restrict__ val, const float* __restrict__ off,
                            const float* __restrict__ aw, const float* __restrict__ refp,
                            float* __restrict__ out) {
    const int bq = blockIdx.x;
    const int b = bq / NQ_;
    const int tid = threadIdx.x;
    const int h = tid >> 5;
    const int hd = tid & 31;
    const float* offr = off + (size_t)bq * 256;
    const float* awr  = aw  + (size_t)bq * 128;
    const float* rr   = refp + (size_t)bq * 8;
    const float* vb   = val + (size_t)b * STOT_ * D_;
    float acc = 0.f;
    const int LVL_W[4]  = {64, 32, 16, 8};
    const int LVL_S0[4] = {0, 4096, 5120, 5376};
    #pragma unroll
    for (int l = 0; l < 4; l++) {
        const int Wl = LVL_W[l];
        const float Wf = (float)Wl;
        const int s0 = LVL_S0[l];
        const float rx = rr[l*2 + 0];
        const float ry = rr[l*2 + 1];
        #pragma unroll
        for (int p = 0; p < 4; p++) {
            const int oi = (((h*4 + l)*4) + p) * 2;
            const float locx = rx + offr[oi + 0] / Wf;
            const float locy = ry + offr[oi + 1] / Wf;   // H == W per level
            const float xx = locx * Wf - 0.5f;
            const float yy = locy * Wf - 0.5f;
            const float x0 = floorf(xx), y0 = floorf(yy);
            const float wx1 = xx - x0, wy1 = yy - y0;
            float sampv = 0.f;
            #pragma unroll
            for (int dy = 0; dy < 2; dy++) {
                const float yi = y0 + (float)dy;
                const float wy = dy ? wy1 : (1.f - wy1);
                #pragma unroll
                for (int dx = 0; dx < 2; dx++) {
                    const float xi = x0 + (float)dx;
                    const float wx = dx ? wx1 : (1.f - wx1);
                    const bool valid = (xi >= 0.f) && (xi <= Wf - 1.f) &&
                                       (yi >= 0.f) && (yi <= Wf - 1.f);
                    const float w = wx * wy * (valid ? 1.f : 0.f);
                    if (w != 0.f) {
                        const int xic = (int)fminf(fmaxf(xi, 0.f), Wf - 1.f);
                        const int yic = (int)fminf(fmaxf(yi, 0.f), Wf - 1.f);
                        const float g = vb[(size_t)(s0 + yic * Wl + xic) * D_ + h * HD_ + hd];
                        sampv += g * w;
                    }
                }
            }
            acc += sampv * awr[h*16 + l*4 + p];
        }
    }
    out[(size_t)bq * D_ + tid] = acc;
}

// ---------------- residual + layernorm: dst = LN(a + b) ----------------
__global__ void ln_kernel(float* __restrict__ dst, const float* __restrict__ a,
                          const float* __restrict__ bsrc, const float* __restrict__ g,
                          const float* __restrict__ beta) {
    const int row = blockIdx.x;
    const int c = threadIdx.x;
    const float v = a[(size_t)row * D_ + c] + bsrc[(size_t)row * D_ + c];
    __shared__ float red[8];
    __shared__ float sh_mu, sh_var;
    float s = v;
    #pragma unroll
    for (int o = 16; o; o >>= 1) s += __shfl_xor_sync(0xffffffffu, s, o);
    if ((c & 31) == 0) red[c >> 5] = s;
    __syncthreads();
    if (c == 0) {
        float t = 0.f;
        #pragma unroll
        for (int i = 0; i < 8; i++) t += red[i];
        sh_mu = t * (1.f / 256.f);
    }
    __syncthreads();
    const float mu = sh_mu;
    const float d = v - mu;
    s = d * d;
    #pragma unroll
    for (int o = 16; o; o >>= 1) s += __shfl_xor_sync(0xffffffffu, s, o);
    if ((c & 31) == 0) red[c >> 5] = s;
    __syncthreads();
    if (c == 0) {
        float t = 0.f;
        #pragma unroll
        for (int i = 0; i < 8; i++) t += red[i];
        sh_var = t * (1.f / 256.f);
    }
    __syncthreads();
    const float y = d * rsqrtf(sh_var + 1e-5f) * g[c] + beta[c];
    dst[(size_t)row * D_ + c] = y;
}

// ---------------- host orchestration ----------------
extern "C" void kernel_launch(void* const* d_in, const int* in_sizes, int n_in,
                              void* d_out, int out_size) {
    (void)in_sizes; (void)n_in; (void)out_size;
    const float* tgt      = (const float*)d_in[0];
    const float* qpos     = (const float*)d_in[1];
    const float* refp     = (const float*)d_in[2];
    const float* src      = (const float*)d_in[3];
    const float* sa_w_q   = (const float*)d_in[4];
    const float* sa_b_q   = (const float*)d_in[5];
    const float* sa_w_k   = (const float*)d_in[6];
    const float* sa_b_k   = (const float*)d_in[7];
    const float* sa_w_v   = (const float*)d_in[8];
    const float* sa_b_v   = (const float*)d_in[9];
    const float* sa_w_o   = (const float*)d_in[10];
    const float* sa_b_o   = (const float*)d_in[11];
    const float* ln2_g    = (const float*)d_in[12];
    const float* ln2_b    = (const float*)d_in[13];
    const float* ca_w_off = (const float*)d_in[14];
    const float* ca_b_off = (const float*)d_in[15];
    const float* ca_w_attn= (const float*)d_in[16];
    const float* ca_b_attn= (const float*)d_in[17];
    const float* ca_w_val = (const float*)d_in[18];
    const float* ca_b_val = (const float*)d_in[19];
    const float* ca_w_out = (const float*)d_in[20];
    const float* ca_b_out = (const float*)d_in[21];
    const float* ln1_g    = (const float*)d_in[22];
    const float* ln1_b    = (const float*)d_in[23];
    const float* ffn_w1   = (const float*)d_in[24];
    const float* ffn_b1   = (const float*)d_in[25];
    const float* ffn_w2   = (const float*)d_in[26];
    const float* ffn_b2   = (const float*)d_in[27];
    const float* ln3_g    = (const float*)d_in[28];
    const float* ln3_b    = (const float*)d_in[29];

    float *x, *q, *qh, *kh, *vh, *t, *t2, *off, *aw, *val, *ffn;
    cudaGetSymbolAddress((void**)&x,   g_x);
    cudaGetSymbolAddress((void**)&q,   g_q);
    cudaGetSymbolAddress((void**)&qh,  g_qh);
    cudaGetSymbolAddress((void**)&kh,  g_kh);
    cudaGetSymbolAddress((void**)&vh,  g_vh);
    cudaGetSymbolAddress((void**)&t,   g_t);
    cudaGetSymbolAddress((void**)&t2,  g_t2);
    cudaGetSymbolAddress((void**)&off, g_off);
    cudaGetSymbolAddress((void**)&aw,  g_aw);
    cudaGetSymbolAddress((void**)&val, g_val);
    cudaGetSymbolAddress((void**)&ffn, g_ffn);

    const int EW_BLOCKS = (XSZ_ + 255) / 256;
    copy_kernel<<<EW_BLOCKS, 256>>>(x, tgt, XSZ_);

    const dim3 G256(D_/64, MROWS_/128);     // (4, 25)   N=256
    const dim3 G128(128/64, MROWS_/128);    // (2, 25)   N=128
    const dim3 G1024(DFFN_/64, MROWS_/128); // (16, 25)  N=1024
    const dim3 GVAL(D_/64, MSRC_/128);      // (4, 85)
    const dim3 GATTN(NQ_/32, H_, B_);       // (50, 8, 2)

    for (int i = 0; i < NLAYERS_; i++) {
        const float* wq = sa_w_q + (size_t)i*D_*D_;   const float* bq = sa_b_q + i*D_;
        const float* wk = sa_w_k + (size_t)i*D_*D_;   const float* bk = sa_b_k + i*D_;
        const float* wv = sa_w_v + (size_t)i*D_*D_;   const float* bv = sa_b_v + i*D_;
        const float* wo = sa_w_o + (size_t)i*D_*D_;   const float* bo = sa_b_o + i*D_;
        const float* woff = ca_w_off + (size_t)i*D_*D_;     const float* boff = ca_b_off + i*D_;
        const float* watt = ca_w_attn + (size_t)i*128*D_;   const float* batt = ca_b_attn + i*128;
        const float* wval = ca_w_val + (size_t)i*D_*D_;     const float* bval = ca_b_val + i*D_;
        const float* wco  = ca_w_out + (size_t)i*D_*D_;     const float* bco  = ca_b_out + i*D_;
        const float* w1 = ffn_w1 + (size_t)i*DFFN_*D_;      const float* b1 = ffn_b1 + i*DFFN_;
        const float* w2 = ffn_w2 + (size_t)i*D_*DFFN_;      const float* b2 = ffn_b2 + i*D_;

        // ---- self attention ----
        add_kernel<<<EW_BLOCKS, 256>>>(q, x, qpos, XSZ_);
        gemm2_kernel<false><<<G256, 256>>>(q, wq, bq, qh, MROWS_, D_, D_);
        gemm2_kernel<false><<<G256, 256>>>(q, wk, bk, kh, MROWS_, D_, D_);
        gemm2_kernel<false><<<G256, 256>>>(x, wv, bv, vh, MROWS_, D_, D_);
        attn2_kernel<<<GATTN, 256>>>(qh, kh, vh, t);
        gemm2_kernel<false><<<G256, 256>>>(t, wo, bo, t2, MROWS_, D_, D_);
        ln_kernel<<<MROWS_, 256>>>(x, x, t2, ln2_g + i*D_, ln2_b + i*D_);

        // ---- deformable cross attention ----
        add_kernel<<<EW_BLOCKS, 256>>>(q, x, qpos, XSZ_);
        gemm2_kernel<false><<<GVAL, 256>>>(src, wval, bval, val, MSRC_, D_, D_);
        gemm2_kernel<false><<<G256, 256>>>(q, woff, boff, off, MROWS_, D_, D_);
        gemm2_kernel<false><<<G128, 256>>>(q, watt, batt, aw, MROWS_, 128, D_);
        softmax16_kernel<<<(MROWS_*H_ + 255)/256, 256>>>(aw, MROWS_*H_);
        msda_kernel<<<MROWS_, 256>>>(val, off, aw, refp, t);
        gemm2_kernel<false><<<G256, 256>>>(t, wco, bco, t2, MROWS_, D_, D_);
        ln_kernel<<<MROWS_, 256>>>(x, x, t2, ln1_g + i*D_, ln1_b + i*D_);

        // ---- FFN ----
        gemm2_kernel<true ><<<G1024, 256>>>(x, w1, b1, ffn, MROWS_, DFFN_, D_);
        gemm2_kernel<false><<<G256,  256>>>(ffn, w2, b2, t2, MROWS_, D_, DFFN_);
        float* dst = (i == NLAYERS_ - 1) ? (float*)d_out : x;
        ln_kernel<<<MROWS_, 256>>>(dst, x, t2, ln3_g + i*D_, ln3_b + i*D_);
    }
}